// round 11
// baseline (speedup 1.0000x reference)
#include <cuda_runtime.h>
#include <cuda_fp16.h>
#include <cstdint>
#include <cstddef>

// ---------------------------------------------------------------------------
// Problem dims
// ---------------------------------------------------------------------------
#define B_DIM 4096
#define H_DIM 1024
#define N_DIM 4096              // 4*H
// fp16 2-term split (hi+lo vs hi): 4 segments of 1024 (x_hi,x_lo,h_hi,h_lo)
#define KEXT  4096
#define KROW_U4 512             // uint4 per packed fp16 row (4096*2/16)
#define NCHUNKS 64              // KEXT / 64

// GEMM tiling: CTA 128x128, 4 warps (2x2), warp tile 64x64, 3-stage cp.async
#define BM 128
#define BN 128
#define BK 64
#define STAGES 3
#define ROWB 144                        // padded smem row bytes (64 fp16 + 8 pad)
#define A_STAGE_BYTES (BM * ROWB)       // 18432
#define STAGE_BYTES   (2 * A_STAGE_BYTES) // A + B = 36864
#define GEMM_SMEM     (STAGES * STAGE_BYTES) // 110592
// Epilogue smem reuse: fp32 tile [128][136] (69632 B) + cbias 128 floats
#define EPI_ROWF 136

// ---------------------------------------------------------------------------
// Device scratch (no allocation allowed in kernel_launch)
// ---------------------------------------------------------------------------
__device__ __half g_Aext[(size_t)B_DIM * KEXT];   // 33.6 MB
__device__ __half g_Wext[(size_t)N_DIM * KEXT];   // 33.6 MB  (gate-interleaved rows: j = 4*h + g)
__device__ float  g_cbias[N_DIM];                 // interleaved combined bias
__device__ float  g_mask[B_DIM];

// ---------------------------------------------------------------------------
// PTX helpers (sm_100 base target: mma.sync / ldmatrix / cp.async only)
// ---------------------------------------------------------------------------
__device__ __forceinline__ uint32_t smem_u32(const void* p) {
    return (uint32_t)__cvta_generic_to_shared(p);
}

__device__ __forceinline__ void cp_async16(uint32_t dst, const void* src) {
    asm volatile("cp.async.cg.shared.global [%0], [%1], 16;"
                 :: "r"(dst), "l"(src));
}
__device__ __forceinline__ void cp_async_commit() {
    asm volatile("cp.async.commit_group;" ::: "memory");
}
template <int N>
__device__ __forceinline__ void cp_async_wait() {
    asm volatile("cp.async.wait_group %0;" :: "n"(N) : "memory");
}

__device__ __forceinline__ void ldsm_x4(uint32_t* r, uint32_t addr) {
    asm volatile("ldmatrix.sync.aligned.m8n8.x4.shared.b16 {%0,%1,%2,%3}, [%4];"
                 : "=r"(r[0]), "=r"(r[1]), "=r"(r[2]), "=r"(r[3]) : "r"(addr));
}

__device__ __forceinline__ void mma_f16(float& d0, float& d1, float& d2, float& d3,
                                        uint32_t a0, uint32_t a1, uint32_t a2, uint32_t a3,
                                        uint32_t b0, uint32_t b1) {
    asm volatile(
        "mma.sync.aligned.m16n8k16.row.col.f32.f16.f16.f32 "
        "{%0,%1,%2,%3}, {%4,%5,%6,%7}, {%8,%9}, {%0,%1,%2,%3};"
        : "+f"(d0), "+f"(d1), "+f"(d2), "+f"(d3)
        : "r"(a0), "r"(a1), "r"(a2), "r"(a3), "r"(b0), "r"(b1));
}

// ---------------------------------------------------------------------------
// fp16 hi/lo split
// ---------------------------------------------------------------------------
__device__ __forceinline__ __half hf_hi(float v) {
    return __float2half(v);
}
__device__ __forceinline__ __half hf_lo(float v) {
    float hi = __half2float(__float2half(v));
    return __float2half(v - hi);
}

// ---------------------------------------------------------------------------
// Pack A_ext[b, k]: 4 segments of 1024 cols: x_hi | x_lo | h_hi | h_lo
// grid (8, 4096), 256 threads; 2 cols per thread
// ---------------------------------------------------------------------------
__global__ void pack_a_kernel(const float* __restrict__ x,
                              const float* __restrict__ h) {
    int b = blockIdx.y;
    int p = blockIdx.x * 256 + threadIdx.x;   // 0..2047
    int col = p * 2;
    int seg = col >> 10;
    int off = col & 1023;
    const float* src = (seg >= 2) ? h : x;
    bool want_lo = (seg & 1);
    float v0 = src[(size_t)b * 1024 + off];
    float v1 = src[(size_t)b * 1024 + off + 1];
    __half2 t;
    if (want_lo) { t.x = hf_lo(v0); t.y = hf_lo(v1); }
    else         { t.x = hf_hi(v0); t.y = hf_hi(v1); }
    *reinterpret_cast<__half2*>(g_Aext + (size_t)b * KEXT + col) = t;
}

// ---------------------------------------------------------------------------
// Pack W_ext: GATE-INTERLEAVED rows. Source row (g, hh) -> dest row 4*hh + g.
// 4 K-segments (all hi): Wx_hi | Wx_hi | Wh_hi | Wh_hi   (Wx=W{g}, Wh=V{g})
// grid (8, 4096), 256 threads
// ---------------------------------------------------------------------------
__global__ void pack_w_kernel(const float* __restrict__ Wf, const float* __restrict__ Wi,
                              const float* __restrict__ Wo, const float* __restrict__ Wc,
                              const float* __restrict__ Vf, const float* __restrict__ Vi,
                              const float* __restrict__ Vo, const float* __restrict__ Vc) {
    int j = blockIdx.y;
    int g = j >> 10;
    int hh = j & 1023;
    int p = blockIdx.x * 256 + threadIdx.x;
    int col = p * 2;
    int seg = col >> 10;
    int off = col & 1023;
    const float* Wp = (g == 0) ? Wf : (g == 1) ? Wi : (g == 2) ? Wo : Wc;
    const float* Vp = (g == 0) ? Vf : (g == 1) ? Vi : (g == 2) ? Vo : Vc;
    const float* src = (seg >= 2) ? Vp : Wp;
    float v0 = src[(size_t)hh * 1024 + off];
    float v1 = src[(size_t)hh * 1024 + off + 1];
    __half2 t;
    t.x = hf_hi(v0); t.y = hf_hi(v1);
    int jdst = hh * 4 + g;
    *reinterpret_cast<__half2*>(g_Wext + (size_t)jdst * KEXT + col) = t;
}

// ---------------------------------------------------------------------------
// Combined interleaved bias: g_cbias[4*hh+g] = bW_g[hh] + bV_g[hh] + b_g[hh]
// grid 16, 256 threads
// ---------------------------------------------------------------------------
__global__ void bias_kernel(const float* __restrict__ bWf, const float* __restrict__ bVf, const float* __restrict__ bf_,
                            const float* __restrict__ bWi, const float* __restrict__ bVi, const float* __restrict__ bi_,
                            const float* __restrict__ bWo, const float* __restrict__ bVo, const float* __restrict__ bo_,
                            const float* __restrict__ bWc, const float* __restrict__ bVc, const float* __restrict__ bc_) {
    int j = blockIdx.x * 256 + threadIdx.x;   // 0..4095
    int g = j & 3;
    int hh = j >> 2;
    const float* bW = (g == 0) ? bWf : (g == 1) ? bWi : (g == 2) ? bWo : bWc;
    const float* bV = (g == 0) ? bVf : (g == 1) ? bVi : (g == 2) ? bVo : bVc;
    const float* bb = (g == 0) ? bf_ : (g == 1) ? bi_ : (g == 2) ? bo_ : bc_;
    g_cbias[j] = bW[hh] + bV[hh] + bb[hh];
}

// ---------------------------------------------------------------------------
// Row-norm silence mask: mask[b] = (||x_b||^2 > 1e-6) ? 1 : 0
// ---------------------------------------------------------------------------
__global__ void mask_kernel(const float* __restrict__ x) {
    __shared__ float red[8];
    int b = blockIdx.x;
    float s = 0.f;
    for (int k = threadIdx.x; k < 1024; k += 256) {
        float v = x[(size_t)b * 1024 + k];
        s += v * v;
    }
    #pragma unroll
    for (int o = 16; o; o >>= 1) s += __shfl_xor_sync(0xFFFFFFFFu, s, o);
    if ((threadIdx.x & 31) == 0) red[threadIdx.x >> 5] = s;
    __syncthreads();
    if (threadIdx.x == 0) {
        float t = 0.f;
        #pragma unroll
        for (int i = 0; i < 8; ++i) t += red[i];
        g_mask[b] = (t > 1e-6f) ? 1.f : 0.f;
    }
}

__device__ __forceinline__ float sigm(float z) {
    return 1.f / (1.f + __expf(-z));
}

// ---------------------------------------------------------------------------
// Fused GEMM + LSTM cell.
// gates[4096,4096] = A_ext @ W_ext^T (fp16 mma.sync, fp32 accum), W rows
// gate-interleaved so this CTA's 128 cols = 32 h x 4 gates. After the
// mainloop the acc tile goes through smem ([128][136] fp32) and the LSTM
// activations are applied in-CTA; outputs written directly.
// ---------------------------------------------------------------------------
__global__ void __launch_bounds__(128, 2)
gemm_kernel(const float* __restrict__ c_prev, float* __restrict__ out) {
    extern __shared__ char smem[];
    const uint32_t sbase = smem_u32(smem);
    const int tid = threadIdx.x;
    const int wid = tid >> 5, lane = tid & 31;
    const int wm = wid >> 1;          // 0..1
    const int wn = wid & 1;           // 0..1
    const int m0 = blockIdx.y * BM;
    const int n0 = blockIdx.x * BN;

    const uint4* __restrict__ gA = reinterpret_cast<const uint4*>(g_Aext);
    const uint4* __restrict__ gW = reinterpret_cast<const uint4*>(g_Wext);

    const int a_row = wm * 64 + (lane & 15);
    const int a_col = (lane >> 4) * 16;
    const int b_row = wn * 64 + (lane & 7) + ((lane >> 3) & 1) * 8;
    const int b_col = ((lane >> 4) & 1) * 16;

    float acc[4][8][4];
    #pragma unroll
    for (int i = 0; i < 4; ++i)
        #pragma unroll
        for (int j = 0; j < 8; ++j)
            #pragma unroll
            for (int q = 0; q < 4; ++q) acc[i][j][q] = 0.f;

    auto load_stage = [&](int s, int c) {
        uint32_t sA = sbase + s * STAGE_BYTES;
        uint32_t sB = sA + A_STAGE_BYTES;
        #pragma unroll
        for (int i = 0; i < 8; ++i) {
            int id = tid + i * 128;
            int r = id >> 3, q = id & 7;
            cp_async16(sA + r * ROWB + q * 16,
                       gA + (size_t)(m0 + r) * KROW_U4 + (size_t)c * 8 + q);
            cp_async16(sB + r * ROWB + q * 16,
                       gW + (size_t)(n0 + r) * KROW_U4 + (size_t)c * 8 + q);
        }
    };

    #pragma unroll
    for (int s = 0; s < STAGES - 1; ++s) {
        load_stage(s, s);
        cp_async_commit();
    }

    int kc = STAGES - 1;
    #pragma unroll 1
    for (int c = 0; c < NCHUNKS; ++c) {
        cp_async_wait<STAGES - 2>();
        __syncthreads();

        if (kc < NCHUNKS) load_stage(kc % STAGES, kc);
        cp_async_commit();
        ++kc;

        const int s = c % STAGES;
        const uint32_t sA = sbase + s * STAGE_BYTES;
        const uint32_t sB = sA + A_STAGE_BYTES;

        uint32_t aF[2][4][4], bF[2][4][4];
        #pragma unroll
        for (int mi = 0; mi < 4; ++mi)
            ldsm_x4(aF[0][mi], sA + (a_row + mi * 16) * ROWB + a_col);
        #pragma unroll
        for (int nb = 0; nb < 4; ++nb)
            ldsm_x4(bF[0][nb], sB + (b_row + nb * 16) * ROWB + b_col);

        #pragma unroll
        for (int k = 0; k < 4; ++k) {
            const int cur = k & 1;
            const int nxt = cur ^ 1;
            if (k < 3) {
                #pragma unroll
                for (int mi = 0; mi < 4; ++mi)
                    ldsm_x4(aF[nxt][mi],
                            sA + (a_row + mi * 16) * ROWB + (k + 1) * 32 + a_col);
                #pragma unroll
                for (int nb = 0; nb < 4; ++nb)
                    ldsm_x4(bF[nxt][nb],
                            sB + (b_row + nb * 16) * ROWB + (k + 1) * 32 + b_col);
            }
            #pragma unroll
            for (int mi = 0; mi < 4; ++mi) {
                #pragma unroll
                for (int nb = 0; nb < 4; ++nb) {
                    mma_f16(acc[mi][nb * 2 + 0][0], acc[mi][nb * 2 + 0][1],
                            acc[mi][nb * 2 + 0][2], acc[mi][nb * 2 + 0][3],
                            aF[cur][mi][0], aF[cur][mi][1],
                            aF[cur][mi][2], aF[cur][mi][3],
                            bF[cur][nb][0], bF[cur][nb][2]);
                    mma_f16(acc[mi][nb * 2 + 1][0], acc[mi][nb * 2 + 1][1],
                            acc[mi][nb * 2 + 1][2], acc[mi][nb * 2 + 1][3],
                            aF[cur][mi][0], aF[cur][mi][1],
                            aF[cur][mi][2], aF[cur][mi][3],
                            bF[cur][nb][1], bF[cur][nb][3]);
                }
            }
        }
    }

    // ---- Fused LSTM epilogue through smem ----
    __syncthreads();   // all warps done with stage smem before reuse

    float* stile = reinterpret_cast<float*>(smem);       // [128][EPI_ROWF]
    float* scb   = stile + 128 * EPI_ROWF;               // 128 floats

    const int r_base = wm * 64 + (lane >> 2);
    const int c_base = wn * 64 + (lane & 3) * 2;
    #pragma unroll
    for (int mi = 0; mi < 4; ++mi) {
        #pragma unroll
        for (int n8 = 0; n8 < 8; ++n8) {
            int r = r_base + mi * 16;
            int cc = c_base + n8 * 8;
            *reinterpret_cast<float2*>(stile + r * EPI_ROWF + cc) =
                make_float2(acc[mi][n8][0], acc[mi][n8][1]);
            *reinterpret_cast<float2*>(stile + (r + 8) * EPI_ROWF + cc) =
                make_float2(acc[mi][n8][2], acc[mi][n8][3]);
        }
    }
    if (tid < 128) scb[tid] = g_cbias[n0 + tid];
    __syncthreads();

    const int hl = lane;               // h_local 0..31 (warp-lane)
    const int rg = wid;                // row group 0..3
    const int hg = (n0 >> 2) + hl;     // global h index
    float4 cb4 = *reinterpret_cast<float4*>(scb + hl * 4);

    #pragma unroll 1
    for (int rr = 0; rr < 32; ++rr) {
        int row_l = rg * 32 + rr;
        int row = m0 + row_l;
        float4 v = *reinterpret_cast<float4*>(stile + row_l * EPI_ROWF + hl * 4);
        float f  = sigm(v.x + cb4.x);
        float i  = sigm(v.y + cb4.y);
        float o  = sigm(v.z + cb4.z);
        float ct = tanhf(v.w + cb4.w);
        float cp = c_prev[(size_t)row * 1024 + hg];
        float mk = g_mask[row];
        float cn = (f + i) * cp + mk * (i * ct);
        float hn = o * tanhf(cn);
        size_t base = (size_t)row * 1024 + hg;
        out[base] = hn;
        out[4194304 + base] = cn;
        out[8388608 + base] = ct;
    }
}

// ---------------------------------------------------------------------------
// Launcher. Input order = setup_inputs() dict-insertion order:
//   0 x, 1 h_prev, 2 c_prev, 3 c_prev_tilde_dummy,
//   4 Wf, 5 bWf, 6 Vf, 7 bVf,
//   8 Wi, 9 bWi, 10 Vi, 11 bVi,
//   12 Wo, 13 bWo, 14 Vo, 15 bVo,
//   16 Wc, 17 bWc, 18 Vc, 19 bVc,
//   20 bf, 21 bi, 22 bo, 23 bc
// ---------------------------------------------------------------------------
extern "C" void kernel_launch(void* const* d_in, const int* in_sizes, int n_in,
                              void* d_out, int out_size) {
    const float* x      = (const float*)d_in[0];
    const float* h_prev = (const float*)d_in[1];
    const float* c_prev = (const float*)d_in[2];
    const float* Wf  = (const float*)d_in[4];
    const float* bWf = (const float*)d_in[5];
    const float* Vf  = (const float*)d_in[6];
    const float* bVf = (const float*)d_in[7];
    const float* Wi  = (const float*)d_in[8];
    const float* bWi = (const float*)d_in[9];
    const float* Vi  = (const float*)d_in[10];
    const float* bVi = (const float*)d_in[11];
    const float* Wo  = (const float*)d_in[12];
    const float* bWo = (const float*)d_in[13];
    const float* Vo  = (const float*)d_in[14];
    const float* bVo = (const float*)d_in[15];
    const float* Wc  = (const float*)d_in[16];
    const float* bWc = (const float*)d_in[17];
    const float* Vc  = (const float*)d_in[18];
    const float* bVc = (const float*)d_in[19];
    const float* bf_ = (const float*)d_in[20];
    const float* bi_ = (const float*)d_in[21];
    const float* bo_ = (const float*)d_in[22];
    const float* bc_ = (const float*)d_in[23];
    float* out = (float*)d_out;

    cudaFuncSetAttribute(gemm_kernel,
                         cudaFuncAttributeMaxDynamicSharedMemorySize, GEMM_SMEM);

    pack_a_kernel<<<dim3(8, 4096), 256>>>(x, h_prev);
    pack_w_kernel<<<dim3(8, 4096), 256>>>(Wf, Wi, Wo, Wc, Vf, Vi, Vo, Vc);
    bias_kernel<<<16, 256>>>(bWf, bVf, bf_,
                             bWi, bVi, bi_,
                             bWo, bVo, bo_,
                             bWc, bVc, bc_);
    mask_kernel<<<4096, 256>>>(x);
    gemm_kernel<<<dim3(32, 32), 128, GEMM_SMEM>>>(c_prev, out);
}

// round 12
// speedup vs baseline: 1.0851x; 1.0851x over previous
#include <cuda_runtime.h>
#include <cuda_fp16.h>
#include <cstdint>
#include <cstddef>

// ---------------------------------------------------------------------------
// Problem dims
// ---------------------------------------------------------------------------
#define B_DIM 4096
#define H_DIM 1024
#define N_DIM 4096              // 4*H
// fp16 2-term split (hi+lo vs hi): 4 segments of 1024 (x_hi,x_lo,h_hi,h_lo)
#define KEXT  4096
#define KROW_U4 512             // uint4 per packed fp16 row (4096*2/16)
#define NCHUNKS 64              // KEXT / 64

// GEMM tiling: CTA 128x128, 4 warps (2x2), warp tile 64x64, 3-stage cp.async
#define BM 128
#define BN 128
#define BK 64
#define STAGES 3
#define ROWB 144                        // padded smem row bytes (64 fp16 + 8 pad)
#define A_STAGE_BYTES (BM * ROWB)       // 18432
#define STAGE_BYTES   (2 * A_STAGE_BYTES) // A + B = 36864
#define GEMM_SMEM     (STAGES * STAGE_BYTES) // 110592

// prep_kernel block ranges
#define PREP_PACKA_BLOCKS 32768          // 8 x 4096
#define PREP_PACKW_BLOCKS 32768          // 8 x 4096
#define PREP_MASK_BLOCKS  512            // 8 rows per block (warp per row)
#define PREP_TOTAL (PREP_PACKA_BLOCKS + PREP_PACKW_BLOCKS + PREP_MASK_BLOCKS)

// ---------------------------------------------------------------------------
// Device scratch (no allocation allowed in kernel_launch)
// ---------------------------------------------------------------------------
__device__ __half g_Aext[(size_t)B_DIM * KEXT];   // 33.6 MB
__device__ __half g_Wext[(size_t)N_DIM * KEXT];   // 33.6 MB (rows j = gate*1024 + h)
__device__ float  g_gates[(size_t)B_DIM * N_DIM]; // 64 MB
__device__ float  g_mask[B_DIM];

// ---------------------------------------------------------------------------
// PTX helpers (sm_100 base target: mma.sync / ldmatrix / cp.async only)
// ---------------------------------------------------------------------------
__device__ __forceinline__ uint32_t smem_u32(const void* p) {
    return (uint32_t)__cvta_generic_to_shared(p);
}

__device__ __forceinline__ void cp_async16(uint32_t dst, const void* src) {
    asm volatile("cp.async.cg.shared.global [%0], [%1], 16;"
                 :: "r"(dst), "l"(src));
}
__device__ __forceinline__ void cp_async_commit() {
    asm volatile("cp.async.commit_group;" ::: "memory");
}
template <int N>
__device__ __forceinline__ void cp_async_wait() {
    asm volatile("cp.async.wait_group %0;" :: "n"(N) : "memory");
}

__device__ __forceinline__ void ldsm_x4(uint32_t* r, uint32_t addr) {
    asm volatile("ldmatrix.sync.aligned.m8n8.x4.shared.b16 {%0,%1,%2,%3}, [%4];"
                 : "=r"(r[0]), "=r"(r[1]), "=r"(r[2]), "=r"(r[3]) : "r"(addr));
}

__device__ __forceinline__ void mma_f16(float& d0, float& d1, float& d2, float& d3,
                                        uint32_t a0, uint32_t a1, uint32_t a2, uint32_t a3,
                                        uint32_t b0, uint32_t b1) {
    asm volatile(
        "mma.sync.aligned.m16n8k16.row.col.f32.f16.f16.f32 "
        "{%0,%1,%2,%3}, {%4,%5,%6,%7}, {%8,%9}, {%0,%1,%2,%3};"
        : "+f"(d0), "+f"(d1), "+f"(d2), "+f"(d3)
        : "r"(a0), "r"(a1), "r"(a2), "r"(a3), "r"(b0), "r"(b1));
}

// ---------------------------------------------------------------------------
// fp16 hi/lo split
// ---------------------------------------------------------------------------
__device__ __forceinline__ __half hf_hi(float v) {
    return __float2half(v);
}
__device__ __forceinline__ __half hf_lo(float v) {
    float hi = __half2float(__float2half(v));
    return __float2half(v - hi);
}

// ---------------------------------------------------------------------------
// prep_kernel: pack_a + pack_w + mask fused via block-range dispatch.
//   blocks [0, 32768):       A_ext pack (4 segs: x_hi | x_lo | h_hi | h_lo)
//   blocks [32768, 65536):   W_ext pack (rows j=gate*1024+h; segs Wx|Wx|Wh|Wh, all hi)
//   blocks [65536, 66048):   mask, warp-per-row, float4 loads (MLP=8)
// 256 threads/block.
// ---------------------------------------------------------------------------
__global__ void prep_kernel(const float* __restrict__ x,
                            const float* __restrict__ h,
                            const float* __restrict__ Wf, const float* __restrict__ Wi,
                            const float* __restrict__ Wo, const float* __restrict__ Wc,
                            const float* __restrict__ Vf, const float* __restrict__ Vi,
                            const float* __restrict__ Vo, const float* __restrict__ Vc) {
    int bid = blockIdx.x;
    if (bid < PREP_PACKA_BLOCKS) {
        int b = bid >> 3;
        int bx = bid & 7;
        int p = bx * 256 + threadIdx.x;   // 0..2047
        int col = p * 2;
        int seg = col >> 10;
        int off = col & 1023;
        const float* src = (seg >= 2) ? h : x;
        bool want_lo = (seg & 1);
        float v0 = src[(size_t)b * 1024 + off];
        float v1 = src[(size_t)b * 1024 + off + 1];
        __half2 t;
        if (want_lo) { t.x = hf_lo(v0); t.y = hf_lo(v1); }
        else         { t.x = hf_hi(v0); t.y = hf_hi(v1); }
        *reinterpret_cast<__half2*>(g_Aext + (size_t)b * KEXT + col) = t;
    } else if (bid < PREP_PACKA_BLOCKS + PREP_PACKW_BLOCKS) {
        int id = bid - PREP_PACKA_BLOCKS;
        int j = id >> 3;
        int bx = id & 7;
        int g = j >> 10;
        int hh = j & 1023;
        int p = bx * 256 + threadIdx.x;
        int col = p * 2;
        int seg = col >> 10;
        int off = col & 1023;
        const float* Wp = (g == 0) ? Wf : (g == 1) ? Wi : (g == 2) ? Wo : Wc;
        const float* Vp = (g == 0) ? Vf : (g == 1) ? Vi : (g == 2) ? Vo : Vc;
        const float* src = (seg >= 2) ? Vp : Wp;
        float v0 = src[(size_t)hh * 1024 + off];
        float v1 = src[(size_t)hh * 1024 + off + 1];
        __half2 t;
        t.x = hf_hi(v0); t.y = hf_hi(v1);
        *reinterpret_cast<__half2*>(g_Wext + (size_t)j * KEXT + col) = t;
    } else {
        // mask: one warp per batch row, 8 float4 loads per lane
        int w = threadIdx.x >> 5;
        int l = threadIdx.x & 31;
        int r = (bid - PREP_PACKA_BLOCKS - PREP_PACKW_BLOCKS) * 8 + w;
        const float4* xr = reinterpret_cast<const float4*>(x + (size_t)r * 1024);
        float s = 0.f;
        #pragma unroll
        for (int i = 0; i < 8; ++i) {
            float4 v = xr[l + i * 32];
            s += v.x * v.x + v.y * v.y + v.z * v.z + v.w * v.w;
        }
        #pragma unroll
        for (int o = 16; o; o >>= 1) s += __shfl_xor_sync(0xFFFFFFFFu, s, o);
        if (l == 0) g_mask[r] = (s > 1e-6f) ? 1.f : 0.f;
    }
}

// ---------------------------------------------------------------------------
// GEMM: gates[4096,4096] = A_ext @ W_ext^T  (fp16 mma.sync, fp32 accum)
// CTA 128x128, 128 threads (4 warps, 2x2), warp tile 64x64, 3-stage cp.async.
// SMEM rows padded to 144B -> conflict-free ldmatrix, no swizzle.
// ---------------------------------------------------------------------------
__global__ void __launch_bounds__(128, 2)
gemm_kernel() {
    extern __shared__ char smem[];
    const uint32_t sbase = smem_u32(smem);
    const int tid = threadIdx.x;
    const int wid = tid >> 5, lane = tid & 31;
    const int wm = wid >> 1;          // 0..1
    const int wn = wid & 1;           // 0..1
    const int m0 = blockIdx.y * BM;
    const int n0 = blockIdx.x * BN;

    const uint4* __restrict__ gA = reinterpret_cast<const uint4*>(g_Aext);
    const uint4* __restrict__ gW = reinterpret_cast<const uint4*>(g_Wext);

    const int a_row = wm * 64 + (lane & 15);
    const int a_col = (lane >> 4) * 16;
    const int b_row = wn * 64 + (lane & 7) + ((lane >> 3) & 1) * 8;
    const int b_col = ((lane >> 4) & 1) * 16;

    float acc[4][8][4];
    #pragma unroll
    for (int i = 0; i < 4; ++i)
        #pragma unroll
        for (int j = 0; j < 8; ++j)
            #pragma unroll
            for (int q = 0; q < 4; ++q) acc[i][j][q] = 0.f;

    auto load_stage = [&](int s, int c) {
        uint32_t sA = sbase + s * STAGE_BYTES;
        uint32_t sB = sA + A_STAGE_BYTES;
        #pragma unroll
        for (int i = 0; i < 8; ++i) {
            int id = tid + i * 128;
            int r = id >> 3, q = id & 7;
            cp_async16(sA + r * ROWB + q * 16,
                       gA + (size_t)(m0 + r) * KROW_U4 + (size_t)c * 8 + q);
            cp_async16(sB + r * ROWB + q * 16,
                       gW + (size_t)(n0 + r) * KROW_U4 + (size_t)c * 8 + q);
        }
    };

    #pragma unroll
    for (int s = 0; s < STAGES - 1; ++s) {
        load_stage(s, s);
        cp_async_commit();
    }

    int kc = STAGES - 1;
    #pragma unroll 1
    for (int c = 0; c < NCHUNKS; ++c) {
        cp_async_wait<STAGES - 2>();
        __syncthreads();

        if (kc < NCHUNKS) load_stage(kc % STAGES, kc);
        cp_async_commit();
        ++kc;

        const int s = c % STAGES;
        const uint32_t sA = sbase + s * STAGE_BYTES;
        const uint32_t sB = sA + A_STAGE_BYTES;

        uint32_t aF[2][4][4], bF[2][4][4];
        #pragma unroll
        for (int mi = 0; mi < 4; ++mi)
            ldsm_x4(aF[0][mi], sA + (a_row + mi * 16) * ROWB + a_col);
        #pragma unroll
        for (int nb = 0; nb < 4; ++nb)
            ldsm_x4(bF[0][nb], sB + (b_row + nb * 16) * ROWB + b_col);

        #pragma unroll
        for (int k = 0; k < 4; ++k) {
            const int cur = k & 1;
            const int nxt = cur ^ 1;
            if (k < 3) {
                #pragma unroll
                for (int mi = 0; mi < 4; ++mi)
                    ldsm_x4(aF[nxt][mi],
                            sA + (a_row + mi * 16) * ROWB + (k + 1) * 32 + a_col);
                #pragma unroll
                for (int nb = 0; nb < 4; ++nb)
                    ldsm_x4(bF[nxt][nb],
                            sB + (b_row + nb * 16) * ROWB + (k + 1) * 32 + b_col);
            }
            #pragma unroll
            for (int mi = 0; mi < 4; ++mi) {
                #pragma unroll
                for (int nb = 0; nb < 4; ++nb) {
                    mma_f16(acc[mi][nb * 2 + 0][0], acc[mi][nb * 2 + 0][1],
                            acc[mi][nb * 2 + 0][2], acc[mi][nb * 2 + 0][3],
                            aF[cur][mi][0], aF[cur][mi][1],
                            aF[cur][mi][2], aF[cur][mi][3],
                            bF[cur][nb][0], bF[cur][nb][2]);
                    mma_f16(acc[mi][nb * 2 + 1][0], acc[mi][nb * 2 + 1][1],
                            acc[mi][nb * 2 + 1][2], acc[mi][nb * 2 + 1][3],
                            aF[cur][mi][0], aF[cur][mi][1],
                            aF[cur][mi][2], aF[cur][mi][3],
                            bF[cur][nb][1], bF[cur][nb][3]);
                }
            }
        }
    }

    // Write accumulators to gates scratch
    const int mrow = m0 + wm * 64 + (lane >> 2);
    const int ncol = n0 + wn * 64 + (lane & 3) * 2;
    #pragma unroll
    for (int mi = 0; mi < 4; ++mi) {
        #pragma unroll
        for (int n8 = 0; n8 < 8; ++n8) {
            int r0 = mrow + mi * 16;
            int cc = ncol + n8 * 8;
            float* p0 = g_gates + (size_t)r0 * N_DIM + cc;
            float* p1 = g_gates + (size_t)(r0 + 8) * N_DIM + cc;
            *reinterpret_cast<float2*>(p0) = make_float2(acc[mi][n8][0], acc[mi][n8][1]);
            *reinterpret_cast<float2*>(p1) = make_float2(acc[mi][n8][2], acc[mi][n8][3]);
        }
    }
}

// ---------------------------------------------------------------------------
// Fused LSTM epilogue: gates + biases -> activations -> h_next/c_next/c_tilde
// ---------------------------------------------------------------------------
__device__ __forceinline__ float sigm(float z) {
    return 1.f / (1.f + __expf(-z));
}

__global__ void epilogue_kernel(const float* __restrict__ c_prev,
                                const float* __restrict__ bWf, const float* __restrict__ bVf, const float* __restrict__ bf_,
                                const float* __restrict__ bWi, const float* __restrict__ bVi, const float* __restrict__ bi_,
                                const float* __restrict__ bWo, const float* __restrict__ bVo, const float* __restrict__ bo_,
                                const float* __restrict__ bWc, const float* __restrict__ bVc, const float* __restrict__ bc_,
                                float* __restrict__ out) {
    int b = blockIdx.x;
    int h = threadIdx.x * 4;
    const float* grow = g_gates + (size_t)b * N_DIM;

    float4 gf = *reinterpret_cast<const float4*>(grow + h);
    float4 gi = *reinterpret_cast<const float4*>(grow + 1024 + h);
    float4 go = *reinterpret_cast<const float4*>(grow + 2048 + h);
    float4 gc = *reinterpret_cast<const float4*>(grow + 3072 + h);

    float4 bff = *reinterpret_cast<const float4*>(bWf + h);
    float4 bfv = *reinterpret_cast<const float4*>(bVf + h);
    float4 bfe = *reinterpret_cast<const float4*>(bf_ + h);
    float4 bif = *reinterpret_cast<const float4*>(bWi + h);
    float4 biv = *reinterpret_cast<const float4*>(bVi + h);
    float4 bie = *reinterpret_cast<const float4*>(bi_ + h);
    float4 bof = *reinterpret_cast<const float4*>(bWo + h);
    float4 bov = *reinterpret_cast<const float4*>(bVo + h);
    float4 boe = *reinterpret_cast<const float4*>(bo_ + h);
    float4 bcf = *reinterpret_cast<const float4*>(bWc + h);
    float4 bcv = *reinterpret_cast<const float4*>(bVc + h);
    float4 bce = *reinterpret_cast<const float4*>(bc_ + h);

    float4 cp = *reinterpret_cast<const float4*>(c_prev + (size_t)b * 1024 + h);
    float msk = g_mask[b];

    float F[4]  = {gf.x + bff.x + bfv.x + bfe.x, gf.y + bff.y + bfv.y + bfe.y,
                   gf.z + bff.z + bfv.z + bfe.z, gf.w + bff.w + bfv.w + bfe.w};
    float In[4] = {gi.x + bif.x + biv.x + bie.x, gi.y + bif.y + biv.y + bie.y,
                   gi.z + bif.z + biv.z + bie.z, gi.w + bif.w + biv.w + bie.w};
    float O[4]  = {go.x + bof.x + bov.x + boe.x, go.y + bof.y + bov.y + boe.y,
                   go.z + bof.z + bov.z + boe.z, go.w + bof.w + bov.w + boe.w};
    float C[4]  = {gc.x + bcf.x + bcv.x + bce.x, gc.y + bcf.y + bcv.y + bce.y,
                   gc.z + bcf.z + bcv.z + bce.z, gc.w + bcf.w + bcv.w + bce.w};
    float CP[4] = {cp.x, cp.y, cp.z, cp.w};

    float hn[4], cn[4], ct[4];
    #pragma unroll
    for (int j = 0; j < 4; ++j) {
        float f = sigm(F[j]);
        float i = sigm(In[j]);
        float o = sigm(O[j]);
        float c_t = tanhf(C[j]);
        float c_n = (f + i) * CP[j] + msk * (i * c_t);
        hn[j] = o * tanhf(c_n);
        cn[j] = c_n;
        ct[j] = c_t;
    }
    size_t base = (size_t)b * 1024 + h;
    *reinterpret_cast<float4*>(out + base) =
        make_float4(hn[0], hn[1], hn[2], hn[3]);
    *reinterpret_cast<float4*>(out + 4194304 + base) =
        make_float4(cn[0], cn[1], cn[2], cn[3]);
    *reinterpret_cast<float4*>(out + 8388608 + base) =
        make_float4(ct[0], ct[1], ct[2], ct[3]);
}

// ---------------------------------------------------------------------------
// Launcher. Input order = setup_inputs() dict-insertion order:
//   0 x, 1 h_prev, 2 c_prev, 3 c_prev_tilde_dummy,
//   4 Wf, 5 bWf, 6 Vf, 7 bVf,
//   8 Wi, 9 bWi, 10 Vi, 11 bVi,
//   12 Wo, 13 bWo, 14 Vo, 15 bVo,
//   16 Wc, 17 bWc, 18 Vc, 19 bVc,
//   20 bf, 21 bi, 22 bo, 23 bc
// ---------------------------------------------------------------------------
extern "C" void kernel_launch(void* const* d_in, const int* in_sizes, int n_in,
                              void* d_out, int out_size) {
    const float* x      = (const float*)d_in[0];
    const float* h_prev = (const float*)d_in[1];
    const float* c_prev = (const float*)d_in[2];
    const float* Wf  = (const float*)d_in[4];
    const float* bWf = (const float*)d_in[5];
    const float* Vf  = (const float*)d_in[6];
    const float* bVf = (const float*)d_in[7];
    const float* Wi  = (const float*)d_in[8];
    const float* bWi = (const float*)d_in[9];
    const float* Vi  = (const float*)d_in[10];
    const float* bVi = (const float*)d_in[11];
    const float* Wo  = (const float*)d_in[12];
    const float* bWo = (const float*)d_in[13];
    const float* Vo  = (const float*)d_in[14];
    const float* bVo = (const float*)d_in[15];
    const float* Wc  = (const float*)d_in[16];
    const float* bWc = (const float*)d_in[17];
    const float* Vc  = (const float*)d_in[18];
    const float* bVc = (const float*)d_in[19];
    const float* bf_ = (const float*)d_in[20];
    const float* bi_ = (const float*)d_in[21];
    const float* bo_ = (const float*)d_in[22];
    const float* bc_ = (const float*)d_in[23];
    float* out = (float*)d_out;

    cudaFuncSetAttribute(gemm_kernel,
                         cudaFuncAttributeMaxDynamicSharedMemorySize, GEMM_SMEM);

    prep_kernel<<<PREP_TOTAL, 256>>>(x, h_prev,
                                     Wf, Wi, Wo, Wc, Vf, Vi, Vo, Vc);
    gemm_kernel<<<dim3(32, 32), 128, GEMM_SMEM>>>();
    epilogue_kernel<<<4096, 256>>>(c_prev,
                                   bWf, bVf, bf_,
                                   bWi, bVi, bi_,
                                   bWo, bVo, bo_,
                                   bWc, bVc, bc_,
                                   out);
}